// round 9
// baseline (speedup 1.0000x reference)
#include <cuda_runtime.h>
#include <cuda_fp16.h>
#include <cstdint>
#include <math.h>

#define NB 4
#define NS 2048
#define ND 1024
#define NH 4096
#define NC 32000
#define LN_EPS 1e-5f

// -------------------- scratch --------------------
__device__ __half g_h  [(size_t)NB*NS*ND];
__device__ __half g_qkv[(size_t)3*NB*NS*ND];     // packed Q|K|V outputs
__device__ __half g_p  [(size_t)NB*NS*NS];
__device__ __half g_xn [(size_t)NB*NS*ND];
__device__ __half g_hid[(size_t)NB*NS*NH];
__device__ float  g_a  [(size_t)NB*NS*ND];
__device__ float  g_scores[(size_t)NB*NS*NS];
__device__ __half g_wqkvH[(size_t)3*ND*ND];      // packed Qw|Kw|Vw fp16
__device__ __half g_w1H[(size_t)ND*NH];
__device__ __half g_w2H[(size_t)NH*NC];

// -------------------- helpers --------------------
__device__ __forceinline__ uint32_t cvta_shared(const void* p) {
    uint32_t a;
    asm("{ .reg .u64 t; cvta.to.shared.u64 t, %1; cvt.u32.u64 %0, t; }" : "=r"(a) : "l"(p));
    return a;
}
#define CP_ASYNC16(dst, src) asm volatile("cp.async.cg.shared.global [%0], [%1], 16;" :: "r"(dst), "l"(src) : "memory")
#define CP_COMMIT()          asm volatile("cp.async.commit_group;" ::: "memory")

__device__ __forceinline__ void ldsm_x4(uint32_t& r0, uint32_t& r1, uint32_t& r2, uint32_t& r3, uint32_t a) {
    asm volatile("ldmatrix.sync.aligned.m8n8.x4.shared.b16 {%0,%1,%2,%3}, [%4];"
                 : "=r"(r0), "=r"(r1), "=r"(r2), "=r"(r3) : "r"(a));
}
__device__ __forceinline__ void ldsm_x4_t(uint32_t& r0, uint32_t& r1, uint32_t& r2, uint32_t& r3, uint32_t a) {
    asm volatile("ldmatrix.sync.aligned.m8n8.x4.trans.shared.b16 {%0,%1,%2,%3}, [%4];"
                 : "=r"(r0), "=r"(r1), "=r"(r2), "=r"(r3) : "r"(a));
}
__device__ __forceinline__ void mma_f16(float* d, const uint32_t* a, const uint32_t* b) {
    asm volatile(
        "mma.sync.aligned.m16n8k16.row.col.f32.f16.f16.f32 "
        "{%0,%1,%2,%3}, {%4,%5,%6,%7}, {%8,%9}, {%0,%1,%2,%3};"
        : "+f"(d[0]), "+f"(d[1]), "+f"(d[2]), "+f"(d[3])
        : "r"(a[0]), "r"(a[1]), "r"(a[2]), "r"(a[3]), "r"(b[0]), "r"(b[1]));
}

// -------------------- fp16 mma GEMM --------------------
// C[M,N] = alpha * A[M,K] @ B (+bias) (+relu), batched over z. fp16 in, fp32 acc.
//   BNK=true : B is [N,K] half, K-contiguous  -> C = A @ B^T
//   BNK=false: B is [K,N] half, N-contiguous  -> C = A @ B
//   OUTH     : write C as half (RNE) else float
// BM=128, BN=128, BK=64, 128 threads (4 warps, 64x64 warp tiles), 3-stage
// cp.async, k-step double-buffered fragments with ldsm/MMA interleave.
// 2 CTAs/SM. Requires M%128==0, N%128==0, K%64==0.
template<bool BNK, bool BIAS, bool RELU, bool CAUSAL, bool OUTH>
__global__ void __launch_bounds__(128, 2)
mma_gemm(const __half* __restrict__ A, const __half* __restrict__ B,
         const float* __restrict__ bias, void* __restrict__ Cv,
         int M, int N, int K, float alpha,
         long long sA, long long sB, long long sC) {
    constexpr int BM = 128, BN = 128, BK = 64;
    constexpr int AST = BK + 8;                     // 72 halves per A row
    constexpr int BSTK = BK + 8;                    // 72 halves per B row, BNK
    constexpr int BSTN = BN + 8;                    // 136 halves per B row, KN
    constexpr int ASZH = BM * AST;                  // 9216 halves
    constexpr int BSZH = BNK ? BN * BSTK : BK * BSTN;
    constexpr int STGB = (ASZH + BSZH) * 2;         // bytes per stage

    // grid swizzle: supertiles of 16 M-tiles for L2 reuse of B
    const int Mtiles = M >> 7, Ntiles = N >> 7;
    int lin = blockIdx.x;
    int G = Mtiles < 16 ? Mtiles : 16;
    int per = G * Ntiles;
    int grp = lin / per;
    int rem = lin - grp * per;
    int mt0 = grp * G;
    int Gc = (Mtiles - mt0) < G ? (Mtiles - mt0) : G;
    const int m0 = (mt0 + rem % Gc) * BM;
    const int n0 = (rem / Gc) * BN;
    if (CAUSAL && n0 >= m0 + BM) return;

    A += (long long)blockIdx.z * sA;
    B += (long long)blockIdx.z * sB;

    extern __shared__ __half sm[];
    const uint32_t smb = cvta_shared(sm);

    const int tid  = threadIdx.x;
    const int wid  = tid >> 5;
    const int lane = tid & 31;
    const int wm   = (wid & 1) * 64;
    const int wn   = (wid >> 1) * 64;
    const int g    = lane >> 3;       // ldmatrix lane group 0..3
    const int lr   = lane & 7;
    const int cg   = lane >> 2;       // mma c-frag group 0..7
    const int ct   = lane & 3;

    const int nk = K / BK;

    auto load_chunk = [&](int c, int s) {
        const uint32_t sAd = smb + s * STGB;
        const uint32_t sBd = sAd + ASZH * 2;
        const __half* gA = A + (size_t)m0 * K + (size_t)c * BK;
        #pragma unroll
        for (int i = 0; i < 8; i++) {                  // A: 1024 chunks of 16B (128 rows x 8)
            int ch = tid + i * 128;
            int row = ch >> 3, c8 = (ch & 7) * 8;
            CP_ASYNC16(sAd + (uint32_t)(row * AST + c8) * 2,
                       gA + (size_t)row * K + c8);
        }
        if (BNK) {
            const __half* gB = B + (size_t)n0 * K + (size_t)c * BK;
            #pragma unroll
            for (int i = 0; i < 8; i++) {              // 1024 chunks: 128 rows x 8
                int ch = tid + i * 128;
                int row = ch >> 3, c8 = (ch & 7) * 8;
                CP_ASYNC16(sBd + (uint32_t)(row * BSTK + c8) * 2,
                           gB + (size_t)row * K + c8);
            }
        } else {
            const __half* gB = B + (size_t)c * BK * N + n0;
            #pragma unroll
            for (int i = 0; i < 8; i++) {              // 1024 chunks: 64 rows x 16
                int ch = tid + i * 128;
                int row = ch >> 4, c8 = (ch & 15) * 8;
                CP_ASYNC16(sBd + (uint32_t)(row * BSTN + c8) * 2,
                           gB + (size_t)row * N + c8);
            }
        }
        CP_COMMIT();
    };

    float acc[4][8][4];
    #pragma unroll
    for (int im = 0; im < 4; im++)
        #pragma unroll
        for (int jn = 0; jn < 8; jn++)
            #pragma unroll
            for (int r = 0; r < 4; r++) acc[im][jn][r] = 0.f;

    // double-buffered fragments (k-step granularity)
    uint32_t af[2][4][4];
    uint32_t bf[2][8][2];

    load_chunk(0, 0);
    if (nk > 1) load_chunk(1, 1);

    for (int i = 0; i < nk; i++) {
        if (i == nk - 1) asm volatile("cp.async.wait_group 0;" ::: "memory");
        else             asm volatile("cp.async.wait_group 1;" ::: "memory");
        __syncthreads();
        if (i + 2 < nk) load_chunk(i + 2, (i + 2) % 3);

        const uint32_t sAd = smb + (i % 3) * STGB;
        const uint32_t sBd = sAd + ASZH * 2;

        auto ldA1 = [&](int ks, int buf, int im) {
            const int row = wm + im * 16 + lr + ((g & 1) << 3);
            const int col = ks * 16 + ((g >> 1) << 3);
            ldsm_x4(af[buf][im][0], af[buf][im][1], af[buf][im][2], af[buf][im][3],
                    sAd + (uint32_t)(row * AST + col) * 2);
        };
        auto ldB1 = [&](int ks, int buf, int jp) {
            if (BNK) {
                const int n = wn + jp * 16 + lr + ((g >> 1) << 3);
                const int col = ks * 16 + ((g & 1) << 3);
                ldsm_x4(bf[buf][2*jp][0], bf[buf][2*jp][1],
                        bf[buf][2*jp+1][0], bf[buf][2*jp+1][1],
                        sBd + (uint32_t)(n * BSTK + col) * 2);
            } else {
                const int krow = ks * 16 + ((g & 1) << 3) + lr;
                const int ncol = wn + jp * 16 + ((g >> 1) << 3);
                ldsm_x4_t(bf[buf][2*jp][0], bf[buf][2*jp][1],
                          bf[buf][2*jp+1][0], bf[buf][2*jp+1][1],
                          sBd + (uint32_t)(krow * BSTN + ncol) * 2);
            }
        };

        // k-step 0 fragments
        #pragma unroll
        for (int jp = 0; jp < 4; jp++) ldB1(0, 0, jp);
        #pragma unroll
        for (int im = 0; im < 4; im++) ldA1(0, 0, im);

        #pragma unroll
        for (int ks = 0; ks < 4; ks++) {
            const int b = ks & 1, nb = b ^ 1;
            #pragma unroll
            for (int im = 0; im < 4; im++) {
                // interleave next k-step loads between MMA groups (B first:
                // all B frags + A[0] are needed by the next k-step's first group)
                if (ks < 3) {
                    if      (im == 0) { ldB1(ks + 1, nb, 0); ldB1(ks + 1, nb, 1); }
                    else if (im == 1) { ldB1(ks + 1, nb, 2); ldB1(ks + 1, nb, 3); }
                    else if (im == 2) { ldA1(ks + 1, nb, 0); ldA1(ks + 1, nb, 1); }
                    else              { ldA1(ks + 1, nb, 2); ldA1(ks + 1, nb, 3); }
                }
                #pragma unroll
                for (int jn = 0; jn < 8; jn++)
                    mma_f16(acc[im][jn], af[b][im], bf[b][jn]);
            }
        }
    }

    // epilogue
    #pragma unroll
    for (int im = 0; im < 4; im++) {
        const int r0 = m0 + wm + im * 16 + cg;
        #pragma unroll
        for (int jn = 0; jn < 8; jn++) {
            const int cb = n0 + wn + jn * 8 + 2 * ct;
            float v0 = acc[im][jn][0] * alpha;
            float v1 = acc[im][jn][1] * alpha;
            float v2 = acc[im][jn][2] * alpha;
            float v3 = acc[im][jn][3] * alpha;
            if (BIAS) {
                float b0 = bias[cb], b1 = bias[cb + 1];
                v0 += b0; v1 += b1; v2 += b0; v3 += b1;
            }
            if (RELU) {
                v0 = fmaxf(v0, 0.f); v1 = fmaxf(v1, 0.f);
                v2 = fmaxf(v2, 0.f); v3 = fmaxf(v3, 0.f);
            }
            if (OUTH) {
                __half* C = (__half*)Cv + (long long)blockIdx.z * sC;
                *(__half2*)&C[(size_t)r0 * N + cb]       = __floats2half2_rn(v0, v1);
                *(__half2*)&C[(size_t)(r0 + 8) * N + cb] = __floats2half2_rn(v2, v3);
            } else {
                float* C = (float*)Cv + (long long)blockIdx.z * sC;
                *(float2*)&C[(size_t)r0 * N + cb]       = make_float2(v0, v1);
                *(float2*)&C[(size_t)(r0 + 8) * N + cb] = make_float2(v2, v3);
            }
        }
    }
}

// -------------------- fused weight fp32->fp16 conversion --------------------
__global__ void conv_weights(const float2* __restrict__ qw, const float2* __restrict__ kw,
                             const float2* __restrict__ vw, const float2* __restrict__ w1,
                             const float2* __restrict__ w2,
                             __half2* __restrict__ oqkv,   // packed 3x [ND,ND]
                             __half2* __restrict__ o1,
                             __half2* __restrict__ o2) {
    constexpr long long NQ = (long long)ND * ND / 2;
    constexpr long long N1 = (long long)ND * NH / 2;
    constexpr long long N2 = (long long)NH * NC / 2;
    constexpr long long P1 = NQ, P2 = 2 * NQ, P3 = 3 * NQ;
    constexpr long long P4 = P3 + N1, TOT = P4 + N2;
    for (long long i = (long long)blockIdx.x * 256 + threadIdx.x; i < TOT;
         i += (long long)gridDim.x * 256) {
        if      (i < P1) oqkv[i] = __float22half2_rn(qw[i]);
        else if (i < P2) oqkv[i] = __float22half2_rn(kw[i - P1]);
        else if (i < P3) oqkv[i] = __float22half2_rn(vw[i - P2]);
        else if (i < P4) o1[i - P3] = __float22half2_rn(w1[i - P3]);
        else             o2[i - P4] = __float22half2_rn(w2[i - P4]);
    }
}

// -------------------- embedding (fp16 out) --------------------
__global__ void embed_kernel(const int* __restrict__ x,
                             const float2* __restrict__ sem,
                             const float2* __restrict__ pos) {
    int idx = blockIdx.x * blockDim.x + threadIdx.x;   // over NB*NS*(ND/2)
    int d2  = idx & (ND / 2 - 1);
    int bs  = idx >> 9;
    int s   = bs & (NS - 1);
    int tok = x[bs];
    float2 a = sem[(size_t)tok * (ND / 2) + d2];
    float2 p = pos[(size_t)s   * (ND / 2) + d2];
    ((__half2*)g_h)[idx] = __floats2half2_rn(a.x + p.x, a.y + p.y);
}

// -------------------- causal softmax: fp32 scores -> fp16 probs --------------------
__global__ void softmax_kernel(const float* __restrict__ scores, __half* __restrict__ probs) {
    const int r = blockIdx.x;
    const int q = r & (NS - 1);
    const float* row = scores + (size_t)r * NS;
    __half* prow = probs + (size_t)r * NS;
    const int tid = threadIdx.x;
    __shared__ float red[256];

    float mx = -1e30f;
    for (int c = tid; c <= q; c += 256) mx = fmaxf(mx, row[c]);
    red[tid] = mx; __syncthreads();
    for (int s = 128; s > 0; s >>= 1) {
        if (tid < s) red[tid] = fmaxf(red[tid], red[tid + s]);
        __syncthreads();
    }
    mx = red[0]; __syncthreads();

    float sum = 0.f;
    for (int c = tid; c <= q; c += 256) sum += expf(row[c] - mx);
    red[tid] = sum; __syncthreads();
    for (int s = 128; s > 0; s >>= 1) {
        if (tid < s) red[tid] += red[tid + s];
        __syncthreads();
    }
    const float inv = 1.f / red[0];
    for (int c = tid; c < NS; c += 256)
        prow[c] = (c <= q) ? __float2half_rn(expf(row[c] - mx) * inv) : __half(0.f);
}

// -------------------- layernorm: fp32 in -> fp16 out --------------------
__global__ void layernorm_kernel(const float* __restrict__ a,
                                 const float* __restrict__ g,
                                 const float* __restrict__ b,
                                 __half* __restrict__ out) {
    const int r = blockIdx.x;
    const float* row = a + (size_t)r * ND;
    __half2* orow = (__half2*)(out + (size_t)r * ND);
    const int tid = threadIdx.x;
    float4 v = ((const float4*)row)[tid];
    float s  = v.x + v.y + v.z + v.w;
    float ss = v.x*v.x + v.y*v.y + v.z*v.z + v.w*v.w;
    __shared__ float rs[256], rss[256];
    rs[tid] = s; rss[tid] = ss; __syncthreads();
    for (int st = 128; st > 0; st >>= 1) {
        if (tid < st) { rs[tid] += rs[tid + st]; rss[tid] += rss[tid + st]; }
        __syncthreads();
    }
    const float mu  = rs[0] * (1.f / ND);
    const float var = rss[0] * (1.f / ND) - mu * mu;
    const float inv = rsqrtf(var + LN_EPS);
    float4 gg = ((const float4*)g)[tid];
    float4 bb = ((const float4*)b)[tid];
    orow[tid*2]   = __floats2half2_rn((v.x - mu) * inv * gg.x + bb.x,
                                      (v.y - mu) * inv * gg.y + bb.y);
    orow[tid*2+1] = __floats2half2_rn((v.z - mu) * inv * gg.z + bb.z,
                                      (v.w - mu) * inv * gg.w + bb.w);
}

// -------------------- host --------------------
static const int SMEM_BNK = 3 * (128 * 72 + 128 * 72) * 2;   // 110592 B
static const int SMEM_KN  = 3 * (128 * 72 + 64 * 136) * 2;   // 107520 B

extern "C" void kernel_launch(void* const* d_in, const int* in_sizes, int n_in,
                              void* d_out, int out_size) {
    const int*   x    = (const int*)  d_in[0];
    const float* sem  = (const float*)d_in[1];
    const float* pos  = (const float*)d_in[2];
    // d_in[3] = F (exact identity -> skipped)
    const float* Qw   = (const float*)d_in[4];
    const float* Kw   = (const float*)d_in[5];
    const float* Vw   = (const float*)d_in[6];
    const float* ln_g = (const float*)d_in[7];
    const float* ln_b = (const float*)d_in[8];
    const float* W1   = (const float*)d_in[9];
    const float* b1   = (const float*)d_in[10];
    const float* W2   = (const float*)d_in[11];
    const float* b2   = (const float*)d_in[12];
    float* out = (float*)d_out;

    __half *h,*qkv,*p,*xn,*hid,*wqkvH,*w1H,*w2H;
    float *a,*sc;
    cudaGetSymbolAddress((void**)&h,    g_h);
    cudaGetSymbolAddress((void**)&qkv,  g_qkv);
    cudaGetSymbolAddress((void**)&p,    g_p);
    cudaGetSymbolAddress((void**)&xn,   g_xn);
    cudaGetSymbolAddress((void**)&hid,  g_hid);
    cudaGetSymbolAddress((void**)&a,    g_a);
    cudaGetSymbolAddress((void**)&sc,   g_scores);
    cudaGetSymbolAddress((void**)&wqkvH,g_wqkvH);
    cudaGetSymbolAddress((void**)&w1H,  g_w1H);
    cudaGetSymbolAddress((void**)&w2H,  g_w2H);

    __half* q = qkv;
    __half* k = qkv + (size_t)NB*NS*ND;
    __half* v = qkv + (size_t)2*NB*NS*ND;

    cudaFuncSetAttribute(mma_gemm<false,false,false,false,true>,  cudaFuncAttributeMaxDynamicSharedMemorySize, SMEM_KN);
    cudaFuncSetAttribute(mma_gemm<true, false,false,true, false>, cudaFuncAttributeMaxDynamicSharedMemorySize, SMEM_BNK);
    cudaFuncSetAttribute(mma_gemm<false,false,false,false,false>, cudaFuncAttributeMaxDynamicSharedMemorySize, SMEM_KN);
    cudaFuncSetAttribute(mma_gemm<false,true, true, false,true>,  cudaFuncAttributeMaxDynamicSharedMemorySize, SMEM_KN);
    cudaFuncSetAttribute(mma_gemm<false,true, false,false,false>, cudaFuncAttributeMaxDynamicSharedMemorySize, SMEM_KN);

    const long long sQKV = (long long)NS * ND;
    const long long sSS  = (long long)NS * NS;

    // 0) weights -> fp16 (one launch; QKV packed contiguously)
    conv_weights<<<65536, 256>>>((const float2*)Qw, (const float2*)Kw, (const float2*)Vw,
                                 (const float2*)W1, (const float2*)W2,
                                 (__half2*)wqkvH, (__half2*)w1H, (__half2*)w2H);

    // 1) embeddings -> fp16
    embed_kernel<<<(NB*NS*ND/2)/256, 256>>>(x, (const float2*)sem, (const float2*)pos);

    // 2) fused QKV projection: z in {Q,K,V}; A shared, B/C strided
    mma_gemm<false,false,false,false,true><<<dim3((NB*NS/128)*(ND/128), 1, 3), 128, SMEM_KN>>>(
        h, wqkvH, nullptr, qkv, NB*NS, ND, ND, 1.f,
        0, (long long)ND*ND, (long long)NB*NS*ND);

    // 3) scores = Q @ K^T / 32 -> fp32 (causal tile skip)
    mma_gemm<true,false,false,true,false><<<dim3((NS/128)*(NS/128), 1, NB), 128, SMEM_BNK>>>(
        q, k, nullptr, sc, NS, NS, ND, 0.03125f, sQKV, sQKV, sSS);

    // 4) causal softmax -> fp16 probs
    softmax_kernel<<<NB*NS, 256>>>(sc, p);

    // 5) a = probs @ Vx -> fp32
    mma_gemm<false,false,false,false,false><<<dim3((NS/128)*(ND/128), 1, NB), 128, SMEM_KN>>>(
        p, v, nullptr, a, NS, ND, NS, 1.f, sSS, sQKV, sQKV);

    // 6) layernorm -> fp16
    layernorm_kernel<<<NB*NS, 256>>>(a, ln_g, ln_b, xn);

    // 7) MLP1: relu(xn @ W1 + b1) -> fp16
    mma_gemm<false,true,true,false,true><<<dim3((NB*NS/128)*(NH/128), 1, 1), 128, SMEM_KN>>>(
        xn, w1H, b1, hid, NB*NS, NH, ND, 1.f, 0, 0, 0);

    // 8) MLP2: hid @ W2 + b2 -> fp32 out
    mma_gemm<false,true,false,false,false><<<dim3((NB*NS/128)*(NC/128), 1, 1), 128, SMEM_KN>>>(
        hid, w2H, b2, out, NB*NS, NC, NH, 1.f, 0, 0, 0);
}

// round 10
// speedup vs baseline: 1.0290x; 1.0290x over previous
#include <cuda_runtime.h>
#include <cuda_fp16.h>
#include <cstdint>
#include <math.h>

#define NB 4
#define NS 2048
#define ND 1024
#define NH 4096
#define NC 32000
#define LN_EPS 1e-5f

// -------------------- scratch --------------------
__device__ __half g_h  [(size_t)NB*NS*ND];
__device__ __half g_qkv[(size_t)3*NB*NS*ND];     // packed Q|K|V outputs
__device__ __half g_p  [(size_t)NB*NS*NS];
__device__ __half g_xn [(size_t)NB*NS*ND];
__device__ __half g_hid[(size_t)NB*NS*NH];
__device__ float  g_a  [(size_t)NB*NS*ND];
__device__ __half g_scores[(size_t)NB*NS*NS];    // fp16 scores
__device__ __half g_wqkvH[(size_t)3*ND*ND];      // packed Qw|Kw|Vw fp16
__device__ __half g_w1H[(size_t)ND*NH];
__device__ __half g_w2H[(size_t)NH*NC];

// -------------------- helpers --------------------
__device__ __forceinline__ uint32_t cvta_shared(const void* p) {
    uint32_t a;
    asm("{ .reg .u64 t; cvta.to.shared.u64 t, %1; cvt.u32.u64 %0, t; }" : "=r"(a) : "l"(p));
    return a;
}
#define CP_ASYNC16(dst, src) asm volatile("cp.async.cg.shared.global [%0], [%1], 16;" :: "r"(dst), "l"(src) : "memory")
#define CP_COMMIT()          asm volatile("cp.async.commit_group;" ::: "memory")

__device__ __forceinline__ void ldsm_x4(uint32_t& r0, uint32_t& r1, uint32_t& r2, uint32_t& r3, uint32_t a) {
    asm volatile("ldmatrix.sync.aligned.m8n8.x4.shared.b16 {%0,%1,%2,%3}, [%4];"
                 : "=r"(r0), "=r"(r1), "=r"(r2), "=r"(r3) : "r"(a));
}
__device__ __forceinline__ void ldsm_x4_t(uint32_t& r0, uint32_t& r1, uint32_t& r2, uint32_t& r3, uint32_t a) {
    asm volatile("ldmatrix.sync.aligned.m8n8.x4.trans.shared.b16 {%0,%1,%2,%3}, [%4];"
                 : "=r"(r0), "=r"(r1), "=r"(r2), "=r"(r3) : "r"(a));
}
__device__ __forceinline__ void mma_f16(float* d, const uint32_t* a, const uint32_t* b) {
    asm volatile(
        "mma.sync.aligned.m16n8k16.row.col.f32.f16.f16.f32 "
        "{%0,%1,%2,%3}, {%4,%5,%6,%7}, {%8,%9}, {%0,%1,%2,%3};"
        : "+f"(d[0]), "+f"(d[1]), "+f"(d[2]), "+f"(d[3])
        : "r"(a[0]), "r"(a[1]), "r"(a[2]), "r"(a[3]), "r"(b[0]), "r"(b[1]));
}

// -------------------- fp16 mma GEMM --------------------
// C[M,N] = alpha * A[M,K] @ B (+bias) (+relu), batched over z. fp16 in, fp32 acc.
//   BNK=true : B is [N,K] half, K-contiguous  -> C = A @ B^T
//   BNK=false: B is [K,N] half, N-contiguous  -> C = A @ B
//   OUTH     : write C as half (RNE) else float
// BM=128, BN=128, BK=64, 128 threads (4 warps, 64x64 warp tiles), 3-stage
// cp.async, k-step double-buffered ldmatrix fragments. 2 CTAs/SM.
template<bool BNK, bool BIAS, bool RELU, bool CAUSAL, bool OUTH>
__global__ void __launch_bounds__(128, 2)
mma_gemm(const __half* __restrict__ A, const __half* __restrict__ B,
         const float* __restrict__ bias, void* __restrict__ Cv,
         int M, int N, int K, float alpha,
         long long sA, long long sB, long long sC) {
    constexpr int BM = 128, BN = 128, BK = 64;
    constexpr int AST = BK + 8;                     // 72 halves per A row
    constexpr int BSTK = BK + 8;                    // 72 halves per B row, BNK
    constexpr int BSTN = BN + 8;                    // 136 halves per B row, KN
    constexpr int ASZH = BM * AST;                  // 9216 halves
    constexpr int BSZH = BNK ? BN * BSTK : BK * BSTN;
    constexpr int STGB = (ASZH + BSZH) * 2;         // bytes per stage

    // grid swizzle: supertiles of 16 M-tiles for L2 reuse of B
    const int Mtiles = M >> 7, Ntiles = N >> 7;
    int lin = blockIdx.x;
    int G = Mtiles < 16 ? Mtiles : 16;
    int per = G * Ntiles;
    int grp = lin / per;
    int rem = lin - grp * per;
    int mt0 = grp * G;
    int Gc = (Mtiles - mt0) < G ? (Mtiles - mt0) : G;
    const int m0 = (mt0 + rem % Gc) * BM;
    const int n0 = (rem / Gc) * BN;
    if (CAUSAL && n0 >= m0 + BM) return;

    A += (long long)blockIdx.z * sA;
    B += (long long)blockIdx.z * sB;

    extern __shared__ __half sm[];
    const uint32_t smb = cvta_shared(sm);

    const int tid  = threadIdx.x;
    const int wid  = tid >> 5;
    const int lane = tid & 31;
    const int wm   = (wid & 1) * 64;
    const int wn   = (wid >> 1) * 64;
    const int g    = lane >> 3;       // ldmatrix lane group 0..3
    const int lr   = lane & 7;
    const int cg   = lane >> 2;       // mma c-frag group 0..7
    const int ct   = lane & 3;

    const int nk = K / BK;

    auto load_chunk = [&](int c, int s) {
        const uint32_t sAd = smb + s * STGB;
        const uint32_t sBd = sAd + ASZH * 2;
        const __half* gA = A + (size_t)m0 * K + (size_t)c * BK;
        #pragma unroll
        for (int i = 0; i < 8; i++) {                  // A: 1024 chunks of 16B (128 rows x 8)
            int ch = tid + i * 128;
            int row = ch >> 3, c8 = (ch & 7) * 8;
            CP_ASYNC16(sAd + (uint32_t)(row * AST + c8) * 2,
                       gA + (size_t)row * K + c8);
        }
        if (BNK) {
            const __half* gB = B + (size_t)n0 * K + (size_t)c * BK;
            #pragma unroll
            for (int i = 0; i < 8; i++) {              // 1024 chunks: 128 rows x 8
                int ch = tid + i * 128;
                int row = ch >> 3, c8 = (ch & 7) * 8;
                CP_ASYNC16(sBd + (uint32_t)(row * BSTK + c8) * 2,
                           gB + (size_t)row * K + c8);
            }
        } else {
            const __half* gB = B + (size_t)c * BK * N + n0;
            #pragma unroll
            for (int i = 0; i < 8; i++) {              // 1024 chunks: 64 rows x 16
                int ch = tid + i * 128;
                int row = ch >> 4, c8 = (ch & 15) * 8;
                CP_ASYNC16(sBd + (uint32_t)(row * BSTN + c8) * 2,
                           gB + (size_t)row * N + c8);
            }
        }
        CP_COMMIT();
    };

    float acc[4][8][4];
    #pragma unroll
    for (int im = 0; im < 4; im++)
        #pragma unroll
        for (int jn = 0; jn < 8; jn++)
            #pragma unroll
            for (int r = 0; r < 4; r++) acc[im][jn][r] = 0.f;

    // double-buffered fragments (k-step granularity)
    uint32_t af[2][4][4];
    uint32_t bf[2][8][2];

    load_chunk(0, 0);
    if (nk > 1) load_chunk(1, 1);

    for (int i = 0; i < nk; i++) {
        if (i == nk - 1) asm volatile("cp.async.wait_group 0;" ::: "memory");
        else             asm volatile("cp.async.wait_group 1;" ::: "memory");
        __syncthreads();

        const uint32_t sAd = smb + (i % 3) * STGB;
        const uint32_t sBd = sAd + ASZH * 2;

        auto ldfrag = [&](int ks, int buf) {
            const int k0 = ks * 16;
            #pragma unroll
            for (int im = 0; im < 4; im++) {
                const int row = wm + im * 16 + lr + ((g & 1) << 3);
                const int col = k0 + ((g >> 1) << 3);
                ldsm_x4(af[buf][im][0], af[buf][im][1], af[buf][im][2], af[buf][im][3],
                        sAd + (uint32_t)(row * AST + col) * 2);
            }
            if (BNK) {
                #pragma unroll
                for (int jp = 0; jp < 4; jp++) {
                    const int n = wn + jp * 16 + lr + ((g >> 1) << 3);
                    const int col = k0 + ((g & 1) << 3);
                    ldsm_x4(bf[buf][2*jp][0], bf[buf][2*jp][1],
                            bf[buf][2*jp+1][0], bf[buf][2*jp+1][1],
                            sBd + (uint32_t)(n * BSTK + col) * 2);
                }
            } else {
                #pragma unroll
                for (int jp = 0; jp < 4; jp++) {
                    const int krow = k0 + ((g & 1) << 3) + lr;
                    const int ncol = wn + jp * 16 + ((g >> 1) << 3);
                    ldsm_x4_t(bf[buf][2*jp][0], bf[buf][2*jp][1],
                              bf[buf][2*jp+1][0], bf[buf][2*jp+1][1],
                              sBd + (uint32_t)(krow * BSTN + ncol) * 2);
                }
            }
        };

        // start k0 fragment loads first (dependent), then next-chunk cp.asyncs
        ldfrag(0, 0);
        if (i + 2 < nk) load_chunk(i + 2, (i + 2) % 3);

        #pragma unroll
        for (int ks = 0; ks < 4; ks++) {
            if (ks < 3) ldfrag(ks + 1, (ks + 1) & 1);
            const int b = ks & 1;
            #pragma unroll
            for (int im = 0; im < 4; im++)
                #pragma unroll
                for (int jn = 0; jn < 8; jn++)
                    mma_f16(acc[im][jn], af[b][im], bf[b][jn]);
        }
    }

    // epilogue
    #pragma unroll
    for (int im = 0; im < 4; im++) {
        const int r0 = m0 + wm + im * 16 + cg;
        #pragma unroll
        for (int jn = 0; jn < 8; jn++) {
            const int cb = n0 + wn + jn * 8 + 2 * ct;
            float v0 = acc[im][jn][0] * alpha;
            float v1 = acc[im][jn][1] * alpha;
            float v2 = acc[im][jn][2] * alpha;
            float v3 = acc[im][jn][3] * alpha;
            if (BIAS) {
                float b0 = bias[cb], b1 = bias[cb + 1];
                v0 += b0; v1 += b1; v2 += b0; v3 += b1;
            }
            if (RELU) {
                v0 = fmaxf(v0, 0.f); v1 = fmaxf(v1, 0.f);
                v2 = fmaxf(v2, 0.f); v3 = fmaxf(v3, 0.f);
            }
            if (OUTH) {
                __half* C = (__half*)Cv + (long long)blockIdx.z * sC;
                *(__half2*)&C[(size_t)r0 * N + cb]       = __floats2half2_rn(v0, v1);
                *(__half2*)&C[(size_t)(r0 + 8) * N + cb] = __floats2half2_rn(v2, v3);
            } else {
                float* C = (float*)Cv + (long long)blockIdx.z * sC;
                *(float2*)&C[(size_t)r0 * N + cb]       = make_float2(v0, v1);
                *(float2*)&C[(size_t)(r0 + 8) * N + cb] = make_float2(v2, v3);
            }
        }
    }
}

// -------------------- fused weight fp32->fp16 conversion --------------------
__global__ void conv_weights(const float2* __restrict__ qw, const float2* __restrict__ kw,
                             const float2* __restrict__ vw, const float2* __restrict__ w1,
                             const float2* __restrict__ w2,
                             __half2* __restrict__ oqkv,   // packed 3x [ND,ND]
                             __half2* __restrict__ o1,
                             __half2* __restrict__ o2) {
    constexpr long long NQ = (long long)ND * ND / 2;
    constexpr long long N1 = (long long)ND * NH / 2;
    constexpr long long N2 = (long long)NH * NC / 2;
    constexpr long long P1 = NQ, P2 = 2 * NQ, P3 = 3 * NQ;
    constexpr long long P4 = P3 + N1, TOT = P4 + N2;
    for (long long i = (long long)blockIdx.x * 256 + threadIdx.x; i < TOT;
         i += (long long)gridDim.x * 256) {
        if      (i < P1) oqkv[i] = __float22half2_rn(qw[i]);
        else if (i < P2) oqkv[i] = __float22half2_rn(kw[i - P1]);
        else if (i < P3) oqkv[i] = __float22half2_rn(vw[i - P2]);
        else if (i < P4) o1[i - P3] = __float22half2_rn(w1[i - P3]);
        else             o2[i - P4] = __float22half2_rn(w2[i - P4]);
    }
}

// -------------------- embedding (fp16 out) --------------------
__global__ void embed_kernel(const int* __restrict__ x,
                             const float2* __restrict__ sem,
                             const float2* __restrict__ pos) {
    int idx = blockIdx.x * blockDim.x + threadIdx.x;   // over NB*NS*(ND/2)
    int d2  = idx & (ND / 2 - 1);
    int bs  = idx >> 9;
    int s   = bs & (NS - 1);
    int tok = x[bs];
    float2 a = sem[(size_t)tok * (ND / 2) + d2];
    float2 p = pos[(size_t)s   * (ND / 2) + d2];
    ((__half2*)g_h)[idx] = __floats2half2_rn(a.x + p.x, a.y + p.y);
}

// -------------------- causal softmax: fp16 scores -> fp16 probs --------------------
// one pass over the row, values cached in registers (8 per thread)
__global__ void softmax_kernel(const __half* __restrict__ scores, __half* __restrict__ probs) {
    const int r = blockIdx.x;
    const int q = r & (NS - 1);
    const __half* row = scores + (size_t)r * NS;
    __half* prow = probs + (size_t)r * NS;
    const int tid = threadIdx.x;
    __shared__ float red[256];

    float v[8];
    float mx = -1e30f;
    #pragma unroll
    for (int j = 0; j < 8; j++) {
        const int c = tid + j * 256;
        v[j] = __half2float(row[c]);
        if (c <= q) mx = fmaxf(mx, v[j]);
    }
    red[tid] = mx; __syncthreads();
    for (int s = 128; s > 0; s >>= 1) {
        if (tid < s) red[tid] = fmaxf(red[tid], red[tid + s]);
        __syncthreads();
    }
    mx = red[0]; __syncthreads();

    float e[8];
    float sum = 0.f;
    #pragma unroll
    for (int j = 0; j < 8; j++) {
        const int c = tid + j * 256;
        e[j] = (c <= q) ? expf(v[j] - mx) : 0.f;
        sum += e[j];
    }
    red[tid] = sum; __syncthreads();
    for (int s = 128; s > 0; s >>= 1) {
        if (tid < s) red[tid] += red[tid + s];
        __syncthreads();
    }
    const float inv = 1.f / red[0];
    #pragma unroll
    for (int j = 0; j < 8; j++)
        prow[tid + j * 256] = __float2half_rn(e[j] * inv);
}

// -------------------- layernorm: fp32 in -> fp16 out --------------------
__global__ void layernorm_kernel(const float* __restrict__ a,
                                 const float* __restrict__ g,
                                 const float* __restrict__ b,
                                 __half* __restrict__ out) {
    const int r = blockIdx.x;
    const float* row = a + (size_t)r * ND;
    __half2* orow = (__half2*)(out + (size_t)r * ND);
    const int tid = threadIdx.x;
    float4 v = ((const float4*)row)[tid];
    float s  = v.x + v.y + v.z + v.w;
    float ss = v.x*v.x + v.y*v.y + v.z*v.z + v.w*v.w;
    __shared__ float rs[256], rss[256];
    rs[tid] = s; rss[tid] = ss; __syncthreads();
    for (int st = 128; st > 0; st >>= 1) {
        if (tid < st) { rs[tid] += rs[tid + st]; rss[tid] += rss[tid + st]; }
        __syncthreads();
    }
    const float mu  = rs[0] * (1.f / ND);
    const float var = rss[0] * (1.f / ND) - mu * mu;
    const float inv = rsqrtf(var + LN_EPS);
    float4 gg = ((const float4*)g)[tid];
    float4 bb = ((const float4*)b)[tid];
    orow[tid*2]   = __floats2half2_rn((v.x - mu) * inv * gg.x + bb.x,
                                      (v.y - mu) * inv * gg.y + bb.y);
    orow[tid*2+1] = __floats2half2_rn((v.z - mu) * inv * gg.z + bb.z,
                                      (v.w - mu) * inv * gg.w + bb.w);
}

// -------------------- host --------------------
static const int SMEM_BNK = 3 * (128 * 72 + 128 * 72) * 2;   // 110592 B
static const int SMEM_KN  = 3 * (128 * 72 + 64 * 136) * 2;   // 107520 B

extern "C" void kernel_launch(void* const* d_in, const int* in_sizes, int n_in,
                              void* d_out, int out_size) {
    const int*   x    = (const int*)  d_in[0];
    const float* sem  = (const float*)d_in[1];
    const float* pos  = (const float*)d_in[2];
    // d_in[3] = F (exact identity -> skipped)
    const float* Qw   = (const float*)d_in[4];
    const float* Kw   = (const float*)d_in[5];
    const float* Vw   = (const float*)d_in[6];
    const float* ln_g = (const float*)d_in[7];
    const float* ln_b = (const float*)d_in[8];
    const float* W1   = (const float*)d_in[9];
    const float* b1   = (const float*)d_in[10];
    const float* W2   = (const float*)d_in[11];
    const float* b2   = (const float*)d_in[12];
    float* out = (float*)d_out;

    __half *h,*qkv,*p,*xn,*hid,*wqkvH,*w1H,*w2H,*sc;
    float *a;
    cudaGetSymbolAddress((void**)&h,    g_h);
    cudaGetSymbolAddress((void**)&qkv,  g_qkv);
    cudaGetSymbolAddress((void**)&p,    g_p);
    cudaGetSymbolAddress((void**)&xn,   g_xn);
    cudaGetSymbolAddress((void**)&hid,  g_hid);
    cudaGetSymbolAddress((void**)&a,    g_a);
    cudaGetSymbolAddress((void**)&sc,   g_scores);
    cudaGetSymbolAddress((void**)&wqkvH,g_wqkvH);
    cudaGetSymbolAddress((void**)&w1H,  g_w1H);
    cudaGetSymbolAddress((void**)&w2H,  g_w2H);

    __half* q = qkv;
    __half* k = qkv + (size_t)NB*NS*ND;
    __half* v = qkv + (size_t)2*NB*NS*ND;

    cudaFuncSetAttribute(mma_gemm<false,false,false,false,true>,  cudaFuncAttributeMaxDynamicSharedMemorySize, SMEM_KN);
    cudaFuncSetAttribute(mma_gemm<true, false,false,true, true>,  cudaFuncAttributeMaxDynamicSharedMemorySize, SMEM_BNK);
    cudaFuncSetAttribute(mma_gemm<false,false,false,false,false>, cudaFuncAttributeMaxDynamicSharedMemorySize, SMEM_KN);
    cudaFuncSetAttribute(mma_gemm<false,true, true, false,true>,  cudaFuncAttributeMaxDynamicSharedMemorySize, SMEM_KN);
    cudaFuncSetAttribute(mma_gemm<false,true, false,false,false>, cudaFuncAttributeMaxDynamicSharedMemorySize, SMEM_KN);

    const long long sQKV = (long long)NS * ND;
    const long long sSS  = (long long)NS * NS;

    // 0) weights -> fp16 (one launch; QKV packed contiguously)
    conv_weights<<<65536, 256>>>((const float2*)Qw, (const float2*)Kw, (const float2*)Vw,
                                 (const float2*)W1, (const float2*)W2,
                                 (__half2*)wqkvH, (__half2*)w1H, (__half2*)w2H);

    // 1) embeddings -> fp16
    embed_kernel<<<(NB*NS*ND/2)/256, 256>>>(x, (const float2*)sem, (const float2*)pos);

    // 2) fused QKV projection: z in {Q,K,V}; A shared, B/C strided
    mma_gemm<false,false,false,false,true><<<dim3((NB*NS/128)*(ND/128), 1, 3), 128, SMEM_KN>>>(
        h, wqkvH, nullptr, qkv, NB*NS, ND, ND, 1.f,
        0, (long long)ND*ND, (long long)NB*NS*ND);

    // 3) scores = Q @ K^T / 32 -> fp16 (causal tile skip)
    mma_gemm<true,false,false,true,true><<<dim3((NS/128)*(NS/128), 1, NB), 128, SMEM_BNK>>>(
        q, k, nullptr, sc, NS, NS, ND, 0.03125f, sQKV, sQKV, sSS);

    // 4) causal softmax -> fp16 probs (single-read, register-cached)
    softmax_kernel<<<NB*NS, 256>>>(sc, p);

    // 5) a = probs @ Vx -> fp32
    mma_gemm<false,false,false,false,false><<<dim3((NS/128)*(ND/128), 1, NB), 128, SMEM_KN>>>(
        p, v, nullptr, a, NS, ND, NS, 1.f, sSS, sQKV, sQKV);

    // 6) layernorm -> fp16
    layernorm_kernel<<<NB*NS, 256>>>(a, ln_g, ln_b, xn);

    // 7) MLP1: relu(xn @ W1 + b1) -> fp16
    mma_gemm<false,true,true,false,true><<<dim3((NB*NS/128)*(NH/128), 1, 1), 128, SMEM_KN>>>(
        xn, w1H, b1, hid, NB*NS, NH, ND, 1.f, 0, 0, 0);

    // 8) MLP2: hid @ W2 + b2 -> fp32 out
    mma_gemm<false,true,false,false,false><<<dim3((NB*NS/128)*(NC/128), 1, 1), 128, SMEM_KN>>>(
        hid, w2H, b2, out, NB*NS, NC, NH, 1.f, 0, 0, 0);
}

// round 11
// speedup vs baseline: 1.1218x; 1.0902x over previous
#include <cuda_runtime.h>
#include <cuda_fp16.h>
#include <cstdint>
#include <math.h>

#define NB 4
#define NS 2048
#define ND 1024
#define NH 4096
#define NC 32000
#define LN_EPS 1e-5f

// -------------------- scratch --------------------
__device__ __half g_h  [(size_t)NB*NS*ND];
__device__ __half g_qkv[(size_t)3*NB*NS*ND];     // packed Q|K|V outputs
__device__ __half g_p  [(size_t)NB*NS*NS];
__device__ __half g_xn [(size_t)NB*NS*ND];
__device__ __half g_hid[(size_t)NB*NS*NH];
__device__ float  g_a  [(size_t)NB*NS*ND];
__device__ __half g_scores[(size_t)NB*NS*NS];    // fp16 scores
__device__ __half g_wqkvH[(size_t)3*ND*ND];      // packed Qw|Kw|Vw fp16
__device__ __half g_w1H[(size_t)ND*NH];
__device__ __half g_w2H[(size_t)NH*NC];

// -------------------- helpers --------------------
__device__ __forceinline__ uint32_t cvta_shared(const void* p) {
    uint32_t a;
    asm("{ .reg .u64 t; cvta.to.shared.u64 t, %1; cvt.u32.u64 %0, t; }" : "=r"(a) : "l"(p));
    return a;
}
#define CP_ASYNC16(dst, src) asm volatile("cp.async.cg.shared.global [%0], [%1], 16;" :: "r"(dst), "l"(src) : "memory")
#define CP_COMMIT()          asm volatile("cp.async.commit_group;" ::: "memory")

__device__ __forceinline__ void ldsm_x4(uint32_t& r0, uint32_t& r1, uint32_t& r2, uint32_t& r3, uint32_t a) {
    asm volatile("ldmatrix.sync.aligned.m8n8.x4.shared.b16 {%0,%1,%2,%3}, [%4];"
                 : "=r"(r0), "=r"(r1), "=r"(r2), "=r"(r3) : "r"(a));
}
__device__ __forceinline__ void ldsm_x4_t(uint32_t& r0, uint32_t& r1, uint32_t& r2, uint32_t& r3, uint32_t a) {
    asm volatile("ldmatrix.sync.aligned.m8n8.x4.trans.shared.b16 {%0,%1,%2,%3}, [%4];"
                 : "=r"(r0), "=r"(r1), "=r"(r2), "=r"(r3) : "r"(a));
}
__device__ __forceinline__ void mma_f16(float* d, const uint32_t* a, const uint32_t* b) {
    asm volatile(
        "mma.sync.aligned.m16n8k16.row.col.f32.f16.f16.f32 "
        "{%0,%1,%2,%3}, {%4,%5,%6,%7}, {%8,%9}, {%0,%1,%2,%3};"
        : "+f"(d[0]), "+f"(d[1]), "+f"(d[2]), "+f"(d[3])
        : "r"(a[0]), "r"(a[1]), "r"(a[2]), "r"(a[3]), "r"(b[0]), "r"(b[1]));
}

// -------------------- fp16 mma GEMM --------------------
// C[M,N] = alpha * A[M,K] @ B (+bias) (+relu), batched over z. fp16 in, fp32 acc.
//   BNK=true : B is [N,K] half, K-contiguous  -> C = A @ B^T
//   BNK=false: B is [K,N] half, N-contiguous  -> C = A @ B
//   CAUSAL   : skip fully-masked N-tiles (n0 >= m0+BM)
//   CK       : causal-K: A rows in tile are zero for k >= m0+BM (probs@V)
//   OUTH     : write C as half (RNE) else float
// BM=128, BN=128, BK=64, 128 threads (4 warps, 64x64 warp tiles), 3-stage
// cp.async, k-step double-buffered ldmatrix fragments with cross-chunk
// prefetch (no chunk-start ldsm bubble). 2 CTAs/SM.
template<bool BNK, bool BIAS, bool RELU, bool CAUSAL, bool CK, bool OUTH>
__global__ void __launch_bounds__(128, 2)
mma_gemm(const __half* __restrict__ A, const __half* __restrict__ B,
         const float* __restrict__ bias, void* __restrict__ Cv,
         int M, int N, int K, float alpha,
         long long sA, long long sB, long long sC) {
    constexpr int BM = 128, BN = 128, BK = 64;
    constexpr int AST = BK + 8;                     // 72 halves per A row
    constexpr int BSTK = BK + 8;                    // 72 halves per B row, BNK
    constexpr int BSTN = BN + 8;                    // 136 halves per B row, KN
    constexpr int ASZH = BM * AST;                  // 9216 halves
    constexpr int BSZH = BNK ? BN * BSTK : BK * BSTN;
    constexpr int STGB = (ASZH + BSZH) * 2;         // bytes per stage

    // grid swizzle: supertiles of 16 M-tiles for L2 reuse of B
    const int Mtiles = M >> 7, Ntiles = N >> 7;
    int lin = blockIdx.x;
    int G = Mtiles < 16 ? Mtiles : 16;
    int per = G * Ntiles;
    int grp = lin / per;
    int rem = lin - grp * per;
    int mt0 = grp * G;
    int Gc = (Mtiles - mt0) < G ? (Mtiles - mt0) : G;
    const int m0 = (mt0 + rem % Gc) * BM;
    const int n0 = (rem / Gc) * BN;
    if (CAUSAL && n0 >= m0 + BM) return;

    A += (long long)blockIdx.z * sA;
    B += (long long)blockIdx.z * sB;

    extern __shared__ __half sm[];
    const uint32_t smb = cvta_shared(sm);

    const int tid  = threadIdx.x;
    const int wid  = tid >> 5;
    const int lane = tid & 31;
    const int wm   = (wid & 1) * 64;
    const int wn   = (wid >> 1) * 64;
    const int g    = lane >> 3;       // ldmatrix lane group 0..3
    const int lr   = lane & 7;
    const int cg   = lane >> 2;       // mma c-frag group 0..7
    const int ct   = lane & 3;

    const int nk = CK ? (m0 + BM) / BK : K / BK;

    auto load_chunk = [&](int c, int s) {
        const uint32_t sAd = smb + s * STGB;
        const uint32_t sBd = sAd + ASZH * 2;
        const __half* gA = A + (size_t)m0 * K + (size_t)c * BK;
        #pragma unroll
        for (int i = 0; i < 8; i++) {                  // A: 1024 chunks of 16B (128 rows x 8)
            int ch = tid + i * 128;
            int row = ch >> 3, c8 = (ch & 7) * 8;
            CP_ASYNC16(sAd + (uint32_t)(row * AST + c8) * 2,
                       gA + (size_t)row * K + c8);
        }
        if (BNK) {
            const __half* gB = B + (size_t)n0 * K + (size_t)c * BK;
            #pragma unroll
            for (int i = 0; i < 8; i++) {              // 1024 chunks: 128 rows x 8
                int ch = tid + i * 128;
                int row = ch >> 3, c8 = (ch & 7) * 8;
                CP_ASYNC16(sBd + (uint32_t)(row * BSTK + c8) * 2,
                           gB + (size_t)row * K + c8);
            }
        } else {
            const __half* gB = B + (size_t)c * BK * N + n0;
            #pragma unroll
            for (int i = 0; i < 8; i++) {              // 1024 chunks: 64 rows x 16
                int ch = tid + i * 128;
                int row = ch >> 4, c8 = (ch & 15) * 8;
                CP_ASYNC16(sBd + (uint32_t)(row * BSTN + c8) * 2,
                           gB + (size_t)row * N + c8);
            }
        }
        CP_COMMIT();
    };

    float acc[4][8][4];
    #pragma unroll
    for (int im = 0; im < 4; im++)
        #pragma unroll
        for (int jn = 0; jn < 8; jn++)
            #pragma unroll
            for (int r = 0; r < 4; r++) acc[im][jn][r] = 0.f;

    // double-buffered fragments (k-step granularity)
    uint32_t af[2][4][4];
    uint32_t bf[2][8][2];

    auto ldfrag = [&](uint32_t sAd, uint32_t sBd, int ks, int buf) {
        const int k0 = ks * 16;
        #pragma unroll
        for (int im = 0; im < 4; im++) {
            const int row = wm + im * 16 + lr + ((g & 1) << 3);
            const int col = k0 + ((g >> 1) << 3);
            ldsm_x4(af[buf][im][0], af[buf][im][1], af[buf][im][2], af[buf][im][3],
                    sAd + (uint32_t)(row * AST + col) * 2);
        }
        if (BNK) {
            #pragma unroll
            for (int jp = 0; jp < 4; jp++) {
                const int n = wn + jp * 16 + lr + ((g >> 1) << 3);
                const int col = k0 + ((g & 1) << 3);
                ldsm_x4(bf[buf][2*jp][0], bf[buf][2*jp][1],
                        bf[buf][2*jp+1][0], bf[buf][2*jp+1][1],
                        sBd + (uint32_t)(n * BSTK + col) * 2);
            }
        } else {
            #pragma unroll
            for (int jp = 0; jp < 4; jp++) {
                const int krow = k0 + ((g & 1) << 3) + lr;
                const int ncol = wn + jp * 16 + ((g >> 1) << 3);
                ldsm_x4_t(bf[buf][2*jp][0], bf[buf][2*jp][1],
                          bf[buf][2*jp+1][0], bf[buf][2*jp+1][1],
                          sBd + (uint32_t)(krow * BSTN + ncol) * 2);
            }
        }
    };
    auto mma_grp = [&](int b) {
        #pragma unroll
        for (int im = 0; im < 4; im++)
            #pragma unroll
            for (int jn = 0; jn < 8; jn++)
                mma_f16(acc[im][jn], af[b][im], bf[b][jn]);
    };

    load_chunk(0, 0);
    if (nk > 1) load_chunk(1, 1);
    if (nk > 1) asm volatile("cp.async.wait_group 1;" ::: "memory");
    else        asm volatile("cp.async.wait_group 0;" ::: "memory");
    __syncthreads();
    ldfrag(smb, smb + ASZH * 2, 0, 0);            // chunk 0, k-step 0 -> buf 0

    for (int i = 0; i < nk; i++) {
        const uint32_t sAd = smb + (i % 3) * STGB;
        const uint32_t sBd = sAd + ASZH * 2;
        // overwrite of stage (i+2)%3 == (i-1)%3 is safe: the ks3-barrier of
        // iter i-1 followed every warp's last read of that stage
        if (i + 2 < nk) load_chunk(i + 2, (i + 2) % 3);

        ldfrag(sAd, sBd, 1, 1); mma_grp(0);
        ldfrag(sAd, sBd, 2, 0); mma_grp(1);
        ldfrag(sAd, sBd, 3, 1); mma_grp(0);
        if (i + 1 < nk) {
            // chunk i+1 resident across ALL warps: per-warp wait + barrier
            if (i + 2 < nk) asm volatile("cp.async.wait_group 1;" ::: "memory");
            else            asm volatile("cp.async.wait_group 0;" ::: "memory");
            __syncthreads();
            const uint32_t nAd = smb + ((i + 1) % 3) * STGB;
            ldfrag(nAd, nAd + ASZH * 2, 0, 0);    // prefetch next chunk k0
            mma_grp(1);                           // last k-step of chunk i
        } else {
            mma_grp(1);
        }
    }

    // epilogue
    #pragma unroll
    for (int im = 0; im < 4; im++) {
        const int r0 = m0 + wm + im * 16 + cg;
        #pragma unroll
        for (int jn = 0; jn < 8; jn++) {
            const int cb = n0 + wn + jn * 8 + 2 * ct;
            float v0 = acc[im][jn][0] * alpha;
            float v1 = acc[im][jn][1] * alpha;
            float v2 = acc[im][jn][2] * alpha;
            float v3 = acc[im][jn][3] * alpha;
            if (BIAS) {
                float b0 = bias[cb], b1 = bias[cb + 1];
                v0 += b0; v1 += b1; v2 += b0; v3 += b1;
            }
            if (RELU) {
                v0 = fmaxf(v0, 0.f); v1 = fmaxf(v1, 0.f);
                v2 = fmaxf(v2, 0.f); v3 = fmaxf(v3, 0.f);
            }
            if (OUTH) {
                __half* C = (__half*)Cv + (long long)blockIdx.z * sC;
                *(__half2*)&C[(size_t)r0 * N + cb]       = __floats2half2_rn(v0, v1);
                *(__half2*)&C[(size_t)(r0 + 8) * N + cb] = __floats2half2_rn(v2, v3);
            } else {
                float* C = (float*)Cv + (long long)blockIdx.z * sC;
                *(float2*)&C[(size_t)r0 * N + cb]       = make_float2(v0, v1);
                *(float2*)&C[(size_t)(r0 + 8) * N + cb] = make_float2(v2, v3);
            }
        }
    }
}

// -------------------- fused weight fp32->fp16 conversion --------------------
__global__ void conv_weights(const float2* __restrict__ qw, const float2* __restrict__ kw,
                             const float2* __restrict__ vw, const float2* __restrict__ w1,
                             const float2* __restrict__ w2,
                             __half2* __restrict__ oqkv,   // packed 3x [ND,ND]
                             __half2* __restrict__ o1,
                             __half2* __restrict__ o2) {
    constexpr long long NQ = (long long)ND * ND / 2;
    constexpr long long N1 = (long long)ND * NH / 2;
    constexpr long long N2 = (long long)NH * NC / 2;
    constexpr long long P1 = NQ, P2 = 2 * NQ, P3 = 3 * NQ;
    constexpr long long P4 = P3 + N1, TOT = P4 + N2;
    for (long long i = (long long)blockIdx.x * 256 + threadIdx.x; i < TOT;
         i += (long long)gridDim.x * 256) {
        if      (i < P1) oqkv[i] = __float22half2_rn(qw[i]);
        else if (i < P2) oqkv[i] = __float22half2_rn(kw[i - P1]);
        else if (i < P3) oqkv[i] = __float22half2_rn(vw[i - P2]);
        else if (i < P4) o1[i - P3] = __float22half2_rn(w1[i - P3]);
        else             o2[i - P4] = __float22half2_rn(w2[i - P4]);
    }
}

// -------------------- embedding (fp16 out) --------------------
__global__ void embed_kernel(const int* __restrict__ x,
                             const float2* __restrict__ sem,
                             const float2* __restrict__ pos) {
    int idx = blockIdx.x * blockDim.x + threadIdx.x;   // over NB*NS*(ND/2)
    int d2  = idx & (ND / 2 - 1);
    int bs  = idx >> 9;
    int s   = bs & (NS - 1);
    int tok = x[bs];
    float2 a = sem[(size_t)tok * (ND / 2) + d2];
    float2 p = pos[(size_t)s   * (ND / 2) + d2];
    ((__half2*)g_h)[idx] = __floats2half2_rn(a.x + p.x, a.y + p.y);
}

// -------------------- causal softmax: fp16 scores -> fp16 probs --------------------
// one pass over the row, values cached in registers (8 per thread)
__global__ void softmax_kernel(const __half* __restrict__ scores, __half* __restrict__ probs) {
    const int r = blockIdx.x;
    const int q = r & (NS - 1);
    const __half* row = scores + (size_t)r * NS;
    __half* prow = probs + (size_t)r * NS;
    const int tid = threadIdx.x;
    __shared__ float red[256];

    float v[8];
    float mx = -1e30f;
    #pragma unroll
    for (int j = 0; j < 8; j++) {
        const int c = tid + j * 256;
        v[j] = __half2float(row[c]);
        if (c <= q) mx = fmaxf(mx, v[j]);
    }
    red[tid] = mx; __syncthreads();
    for (int s = 128; s > 0; s >>= 1) {
        if (tid < s) red[tid] = fmaxf(red[tid], red[tid + s]);
        __syncthreads();
    }
    mx = red[0]; __syncthreads();

    float e[8];
    float sum = 0.f;
    #pragma unroll
    for (int j = 0; j < 8; j++) {
        const int c = tid + j * 256;
        e[j] = (c <= q) ? expf(v[j] - mx) : 0.f;
        sum += e[j];
    }
    red[tid] = sum; __syncthreads();
    for (int s = 128; s > 0; s >>= 1) {
        if (tid < s) red[tid] += red[tid + s];
        __syncthreads();
    }
    const float inv = 1.f / red[0];
    #pragma unroll
    for (int j = 0; j < 8; j++)
        prow[tid + j * 256] = __float2half_rn(e[j] * inv);
}

// -------------------- layernorm: fp32 in -> fp16 out --------------------
__global__ void layernorm_kernel(const float* __restrict__ a,
                                 const float* __restrict__ g,
                                 const float* __restrict__ b,
                                 __half* __restrict__ out) {
    const int r = blockIdx.x;
    const float* row = a + (size_t)r * ND;
    __half2* orow = (__half2*)(out + (size_t)r * ND);
    const int tid = threadIdx.x;
    float4 v = ((const float4*)row)[tid];
    float s  = v.x + v.y + v.z + v.w;
    float ss = v.x*v.x + v.y*v.y + v.z*v.z + v.w*v.w;
    __shared__ float rs[256], rss[256];
    rs[tid] = s; rss[tid] = ss; __syncthreads();
    for (int st = 128; st > 0; st >>= 1) {
        if (tid < st) { rs[tid] += rs[tid + st]; rss[tid] += rss[tid + st]; }
        __syncthreads();
    }
    const float mu  = rs[0] * (1.f / ND);
    const float var = rss[0] * (1.f / ND) - mu * mu;
    const float inv = rsqrtf(var + LN_EPS);
    float4 gg = ((const float4*)g)[tid];
    float4 bb = ((const float4*)b)[tid];
    orow[tid*2]   = __floats2half2_rn((v.x - mu) * inv * gg.x + bb.x,
                                      (v.y - mu) * inv * gg.y + bb.y);
    orow[tid*2+1] = __floats2half2_rn((v.z - mu) * inv * gg.z + bb.z,
                                      (v.w - mu) * inv * gg.w + bb.w);
}

// -------------------- host --------------------
static const int SMEM_BNK = 3 * (128 * 72 + 128 * 72) * 2;   // 110592 B
static const int SMEM_KN  = 3 * (128 * 72 + 64 * 136) * 2;   // 107520 B

extern "C" void kernel_launch(void* const* d_in, const int* in_sizes, int n_in,
                              void* d_out, int out_size) {
    const int*   x    = (const int*)  d_in[0];
    const float* sem  = (const float*)d_in[1];
    const float* pos  = (const float*)d_in[2];
    // d_in[3] = F (exact identity -> skipped)
    const float* Qw   = (const float*)d_in[4];
    const float* Kw   = (const float*)d_in[5];
    const float* Vw   = (const float*)d_in[6];
    const float* ln_g = (const float*)d_in[7];
    const float* ln_b = (const float*)d_in[8];
    const float* W1   = (const float*)d_in[9];
    const float* b1   = (const float*)d_in[10];
    const float* W2   = (const float*)d_in[11];
    const float* b2   = (const float*)d_in[12];
    float* out = (float*)d_out;

    __half *h,*qkv,*p,*xn,*hid,*wqkvH,*w1H,*w2H,*sc;
    float *a;
    cudaGetSymbolAddress((void**)&h,    g_h);
    cudaGetSymbolAddress((void**)&qkv,  g_qkv);
    cudaGetSymbolAddress((void**)&p,    g_p);
    cudaGetSymbolAddress((void**)&xn,   g_xn);
    cudaGetSymbolAddress((void**)&hid,  g_hid);
    cudaGetSymbolAddress((void**)&a,    g_a);
    cudaGetSymbolAddress((void**)&sc,   g_scores);
    cudaGetSymbolAddress((void**)&wqkvH,g_wqkvH);
    cudaGetSymbolAddress((void**)&w1H,  g_w1H);
    cudaGetSymbolAddress((void**)&w2H,  g_w2H);

    __half* q = qkv;
    __half* k = qkv + (size_t)NB*NS*ND;
    __half* v = qkv + (size_t)2*NB*NS*ND;

    cudaFuncSetAttribute(mma_gemm<false,false,false,false,false,true>,  cudaFuncAttributeMaxDynamicSharedMemorySize, SMEM_KN);
    cudaFuncSetAttribute(mma_gemm<true, false,false,true, false,true>,  cudaFuncAttributeMaxDynamicSharedMemorySize, SMEM_BNK);
    cudaFuncSetAttribute(mma_gemm<false,false,false,false,true, false>, cudaFuncAttributeMaxDynamicSharedMemorySize, SMEM_KN);
    cudaFuncSetAttribute(mma_gemm<false,true, true, false,false,true>,  cudaFuncAttributeMaxDynamicSharedMemorySize, SMEM_KN);
    cudaFuncSetAttribute(mma_gemm<false,true, false,false,false,false>, cudaFuncAttributeMaxDynamicSharedMemorySize, SMEM_KN);

    const long long sQKV = (long long)NS * ND;
    const long long sSS  = (long long)NS * NS;

    // 0) weights -> fp16 (one launch; QKV packed contiguously)
    conv_weights<<<65536, 256>>>((const float2*)Qw, (const float2*)Kw, (const float2*)Vw,
                                 (const float2*)W1, (const float2*)W2,
                                 (__half2*)wqkvH, (__half2*)w1H, (__half2*)w2H);

    // 1) embeddings -> fp16
    embed_kernel<<<(NB*NS*ND/2)/256, 256>>>(x, (const float2*)sem, (const float2*)pos);

    // 2) fused QKV projection: z in {Q,K,V}; A shared, B/C strided
    mma_gemm<false,false,false,false,false,true><<<dim3((NB*NS/128)*(ND/128), 1, 3), 128, SMEM_KN>>>(
        h, wqkvH, nullptr, qkv, NB*NS, ND, ND, 1.f,
        0, (long long)ND*ND, (long long)NB*NS*ND);

    // 3) scores = Q @ K^T / 32 -> fp16 (causal tile skip)
    mma_gemm<true,false,false,true,false,true><<<dim3((NS/128)*(NS/128), 1, NB), 128, SMEM_BNK>>>(
        q, k, nullptr, sc, NS, NS, ND, 0.03125f, sQKV, sQKV, sSS);

    // 4) causal softmax -> fp16 probs (single-read, register-cached)
    softmax_kernel<<<NB*NS, 256>>>(sc, p);

    // 5) a = probs @ Vx -> fp32 (causal K-chunk skip)
    mma_gemm<false,false,false,false,true,false><<<dim3((NS/128)*(ND/128), 1, NB), 128, SMEM_KN>>>(
        p, v, nullptr, a, NS, ND, NS, 1.f, sSS, sQKV, sQKV);

    // 6) layernorm -> fp16
    layernorm_kernel<<<NB*NS, 256>>>(a, ln_g, ln_b, xn);

    // 7) MLP1: relu(xn @ W1 + b1) -> fp16
    mma_gemm<false,true,true,false,false,true><<<dim3((NB*NS/128)*(NH/128), 1, 1), 128, SMEM_KN>>>(
        xn, w1H, b1, hid, NB*NS, NH, ND, 1.f, 0, 0, 0);

    // 8) MLP2: hid @ W2 + b2 -> fp32 out
    mma_gemm<false,true,false,false,false,false><<<dim3((NB*NS/128)*(NC/128), 1, 1), 128, SMEM_KN>>>(
        hid, w2H, b2, out, NB*NS, NC, NH, 1.f, 0, 0, 0);
}

// round 12
// speedup vs baseline: 1.1235x; 1.0015x over previous
#include <cuda_runtime.h>
#include <cuda_fp16.h>
#include <cstdint>
#include <math.h>

#define NB 4
#define NS 2048
#define ND 1024
#define NH 4096
#define NC 32000
#define LN_EPS 1e-5f

// -------------------- scratch --------------------
__device__ __half g_h  [(size_t)NB*NS*ND];
__device__ __half g_qkv[(size_t)3*NB*NS*ND];     // packed Q|K|V outputs
__device__ __half g_p  [(size_t)NB*NS*NS];
__device__ __half g_xn [(size_t)NB*NS*ND];
__device__ __half g_hid[(size_t)NB*NS*NH];
__device__ float  g_a  [(size_t)NB*NS*ND];
__device__ __half g_scores[(size_t)NB*NS*NS];    // fp16 scores
__device__ __half g_wqkvH[(size_t)3*ND*ND];      // packed Qw|Kw|Vw fp16
__device__ __half g_w1H[(size_t)ND*NH];
__device__ __half g_w2H[(size_t)NH*NC];

// -------------------- helpers --------------------
__device__ __forceinline__ uint32_t cvta_shared(const void* p) {
    uint32_t a;
    asm("{ .reg .u64 t; cvta.to.shared.u64 t, %1; cvt.u32.u64 %0, t; }" : "=r"(a) : "l"(p));
    return a;
}
#define CP_ASYNC16(dst, src) asm volatile("cp.async.cg.shared.global [%0], [%1], 16;" :: "r"(dst), "l"(src) : "memory")
#define CP_COMMIT()          asm volatile("cp.async.commit_group;" ::: "memory")

__device__ __forceinline__ void ldsm_x4(uint32_t& r0, uint32_t& r1, uint32_t& r2, uint32_t& r3, uint32_t a) {
    asm volatile("ldmatrix.sync.aligned.m8n8.x4.shared.b16 {%0,%1,%2,%3}, [%4];"
                 : "=r"(r0), "=r"(r1), "=r"(r2), "=r"(r3) : "r"(a));
}
__device__ __forceinline__ void ldsm_x4_t(uint32_t& r0, uint32_t& r1, uint32_t& r2, uint32_t& r3, uint32_t a) {
    asm volatile("ldmatrix.sync.aligned.m8n8.x4.trans.shared.b16 {%0,%1,%2,%3}, [%4];"
                 : "=r"(r0), "=r"(r1), "=r"(r2), "=r"(r3) : "r"(a));
}
__device__ __forceinline__ void mma_f16(float* d, const uint32_t* a, const uint32_t* b) {
    asm volatile(
        "mma.sync.aligned.m16n8k16.row.col.f32.f16.f16.f32 "
        "{%0,%1,%2,%3}, {%4,%5,%6,%7}, {%8,%9}, {%0,%1,%2,%3};"
        : "+f"(d[0]), "+f"(d[1]), "+f"(d[2]), "+f"(d[3])
        : "r"(a[0]), "r"(a[1]), "r"(a[2]), "r"(a[3]), "r"(b[0]), "r"(b[1]));
}

// -------------------- fp16 mma GEMM --------------------
// C[M,N] = alpha * A[M,K] @ B (+bias) (+relu), batched over z. fp16 in, fp32 acc.
//   BNK=true : B is [N,K] half, K-contiguous  -> C = A @ B^T
//   BNK=false: B is [K,N] half, N-contiguous  -> C = A @ B
//   TRI      : triangular causal grid (BM==BN): blockIdx.x indexes {(m,n): n<=m}
//   CK       : causal-K: A rows in tile are zero for k >= m0+BM (probs@V)
//   OUTH     : write C as half (RNE) else float
// BM=128, BN=128, BK=64, 128 threads (4 warps, 64x64 warp tiles), 3-stage
// cp.async, k-step double-buffered ldmatrix fragments with cross-chunk
// prefetch. 2 CTAs/SM.
template<bool BNK, bool BIAS, bool RELU, bool TRI, bool CK, bool OUTH>
__global__ void __launch_bounds__(128, 2)
mma_gemm(const __half* __restrict__ A, const __half* __restrict__ B,
         const float* __restrict__ bias, void* __restrict__ Cv,
         int M, int N, int K, float alpha,
         long long sA, long long sB, long long sC, int gsize) {
    constexpr int BM = 128, BN = 128, BK = 64;
    constexpr int AST = BK + 8;                     // 72 halves per A row
    constexpr int BSTK = BK + 8;                    // 72 halves per B row, BNK
    constexpr int BSTN = BN + 8;                    // 136 halves per B row, KN
    constexpr int ASZH = BM * AST;                  // 9216 halves
    constexpr int BSZH = BNK ? BN * BSTK : BK * BSTN;
    constexpr int STGB = (ASZH + BSZH) * 2;         // bytes per stage

    int m0, n0;
    if (TRI) {
        // triangular decode: t -> (m, n), n <= m
        const int t = blockIdx.x;
        int m = (int)((sqrtf(8.f * t + 1.f) - 1.f) * 0.5f);
        while ((m + 1) * (m + 2) / 2 <= t) m++;
        while (m * (m + 1) / 2 > t) m--;
        m0 = m * BM;
        n0 = (t - m * (m + 1) / 2) * BN;
    } else {
        // grid swizzle: supertiles of gsize M-tiles for L2 reuse of B
        const int Mtiles = M >> 7, Ntiles = N >> 7;
        int lin = blockIdx.x;
        int G = Mtiles < gsize ? Mtiles : gsize;
        int per = G * Ntiles;
        int grp = lin / per;
        int rem = lin - grp * per;
        int mt0 = grp * G;
        int Gc = (Mtiles - mt0) < G ? (Mtiles - mt0) : G;
        m0 = (mt0 + rem % Gc) * BM;
        n0 = (rem / Gc) * BN;
    }

    A += (long long)blockIdx.z * sA;
    B += (long long)blockIdx.z * sB;

    extern __shared__ __half sm[];
    const uint32_t smb = cvta_shared(sm);

    const int tid  = threadIdx.x;
    const int wid  = tid >> 5;
    const int lane = tid & 31;
    const int wm   = (wid & 1) * 64;
    const int wn   = (wid >> 1) * 64;
    const int g    = lane >> 3;       // ldmatrix lane group 0..3
    const int lr   = lane & 7;
    const int cg   = lane >> 2;       // mma c-frag group 0..7
    const int ct   = lane & 3;

    const int nk = CK ? (m0 + BM) / BK : K / BK;

    auto load_chunk = [&](int c, int s) {
        const uint32_t sAd = smb + s * STGB;
        const uint32_t sBd = sAd + ASZH * 2;
        const __half* gA = A + (size_t)m0 * K + (size_t)c * BK;
        #pragma unroll
        for (int i = 0; i < 8; i++) {                  // A: 1024 chunks of 16B (128 rows x 8)
            int ch = tid + i * 128;
            int row = ch >> 3, c8 = (ch & 7) * 8;
            CP_ASYNC16(sAd + (uint32_t)(row * AST + c8) * 2,
                       gA + (size_t)row * K + c8);
        }
        if (BNK) {
            const __half* gB = B + (size_t)n0 * K + (size_t)c * BK;
            #pragma unroll
            for (int i = 0; i < 8; i++) {              // 1024 chunks: 128 rows x 8
                int ch = tid + i * 128;
                int row = ch >> 3, c8 = (ch & 7) * 8;
                CP_ASYNC16(sBd + (uint32_t)(row * BSTK + c8) * 2,
                           gB + (size_t)row * K + c8);
            }
        } else {
            const __half* gB = B + (size_t)c * BK * N + n0;
            #pragma unroll
            for (int i = 0; i < 8; i++) {              // 1024 chunks: 64 rows x 16
                int ch = tid + i * 128;
                int row = ch >> 4, c8 = (ch & 15) * 8;
                CP_ASYNC16(sBd + (uint32_t)(row * BSTN + c8) * 2,
                           gB + (size_t)row * N + c8);
            }
        }
        CP_COMMIT();
    };

    float acc[4][8][4];
    #pragma unroll
    for (int im = 0; im < 4; im++)
        #pragma unroll
        for (int jn = 0; jn < 8; jn++)
            #pragma unroll
            for (int r = 0; r < 4; r++) acc[im][jn][r] = 0.f;

    // double-buffered fragments (k-step granularity)
    uint32_t af[2][4][4];
    uint32_t bf[2][8][2];

    auto ldfrag = [&](uint32_t sAd, uint32_t sBd, int ks, int buf) {
        const int k0 = ks * 16;
        #pragma unroll
        for (int im = 0; im < 4; im++) {
            const int row = wm + im * 16 + lr + ((g & 1) << 3);
            const int col = k0 + ((g >> 1) << 3);
            ldsm_x4(af[buf][im][0], af[buf][im][1], af[buf][im][2], af[buf][im][3],
                    sAd + (uint32_t)(row * AST + col) * 2);
        }
        if (BNK) {
            #pragma unroll
            for (int jp = 0; jp < 4; jp++) {
                const int n = wn + jp * 16 + lr + ((g >> 1) << 3);
                const int col = k0 + ((g & 1) << 3);
                ldsm_x4(bf[buf][2*jp][0], bf[buf][2*jp][1],
                        bf[buf][2*jp+1][0], bf[buf][2*jp+1][1],
                        sBd + (uint32_t)(n * BSTK + col) * 2);
            }
        } else {
            #pragma unroll
            for (int jp = 0; jp < 4; jp++) {
                const int krow = k0 + ((g & 1) << 3) + lr;
                const int ncol = wn + jp * 16 + ((g >> 1) << 3);
                ldsm_x4_t(bf[buf][2*jp][0], bf[buf][2*jp][1],
                          bf[buf][2*jp+1][0], bf[buf][2*jp+1][1],
                          sBd + (uint32_t)(krow * BSTN + ncol) * 2);
            }
        }
    };
    auto mma_grp = [&](int b) {
        #pragma unroll
        for (int im = 0; im < 4; im++)
            #pragma unroll
            for (int jn = 0; jn < 8; jn++)
                mma_f16(acc[im][jn], af[b][im], bf[b][jn]);
    };

    load_chunk(0, 0);
    if (nk > 1) load_chunk(1, 1);
    if (nk > 1) asm volatile("cp.async.wait_group 1;" ::: "memory");
    else        asm volatile("cp.async.wait_group 0;" ::: "memory");
    __syncthreads();
    ldfrag(smb, smb + ASZH * 2, 0, 0);            // chunk 0, k-step 0 -> buf 0

    for (int i = 0; i < nk; i++) {
        const uint32_t sAd = smb + (i % 3) * STGB;
        const uint32_t sBd = sAd + ASZH * 2;
        // overwrite of stage (i+2)%3 == (i-1)%3 is safe: the ks3-barrier of
        // iter i-1 followed every warp's last read of that stage
        if (i + 2 < nk) load_chunk(i + 2, (i + 2) % 3);

        ldfrag(sAd, sBd, 1, 1); mma_grp(0);
        ldfrag(sAd, sBd, 2, 0); mma_grp(1);
        ldfrag(sAd, sBd, 3, 1); mma_grp(0);
        if (i + 1 < nk) {
            // chunk i+1 resident across ALL warps: per-warp wait + barrier
            if (i + 2 < nk) asm volatile("cp.async.wait_group 1;" ::: "memory");
            else            asm volatile("cp.async.wait_group 0;" ::: "memory");
            __syncthreads();
            const uint32_t nAd = smb + ((i + 1) % 3) * STGB;
            ldfrag(nAd, nAd + ASZH * 2, 0, 0);    // prefetch next chunk k0
            mma_grp(1);                           // last k-step of chunk i
        } else {
            mma_grp(1);
        }
    }

    // epilogue
    #pragma unroll
    for (int im = 0; im < 4; im++) {
        const int r0 = m0 + wm + im * 16 + cg;
        #pragma unroll
        for (int jn = 0; jn < 8; jn++) {
            const int cb = n0 + wn + jn * 8 + 2 * ct;
            float v0 = acc[im][jn][0] * alpha;
            float v1 = acc[im][jn][1] * alpha;
            float v2 = acc[im][jn][2] * alpha;
            float v3 = acc[im][jn][3] * alpha;
            if (BIAS) {
                float b0 = bias[cb], b1 = bias[cb + 1];
                v0 += b0; v1 += b1; v2 += b0; v3 += b1;
            }
            if (RELU) {
                v0 = fmaxf(v0, 0.f); v1 = fmaxf(v1, 0.f);
                v2 = fmaxf(v2, 0.f); v3 = fmaxf(v3, 0.f);
            }
            if (OUTH) {
                __half* C = (__half*)Cv + (long long)blockIdx.z * sC;
                *(__half2*)&C[(size_t)r0 * N + cb]       = __floats2half2_rn(v0, v1);
                *(__half2*)&C[(size_t)(r0 + 8) * N + cb] = __floats2half2_rn(v2, v3);
            } else {
                float* C = (float*)Cv + (long long)blockIdx.z * sC;
                *(float2*)&C[(size_t)r0 * N + cb]       = make_float2(v0, v1);
                *(float2*)&C[(size_t)(r0 + 8) * N + cb] = make_float2(v2, v3);
            }
        }
    }
}

// -------------------- fused prepass: weights fp32->fp16 + embedding --------------------
__global__ void prepass_kernel(const float2* __restrict__ qw, const float2* __restrict__ kw,
                               const float2* __restrict__ vw, const float2* __restrict__ w1,
                               const float2* __restrict__ w2,
                               const int* __restrict__ x,
                               const float2* __restrict__ sem, const float2* __restrict__ pos,
                               __half2* __restrict__ oqkv,   // packed 3x [ND,ND]
                               __half2* __restrict__ o1,
                               __half2* __restrict__ o2,
                               __half2* __restrict__ oh) {
    constexpr long long NQ = (long long)ND * ND / 2;
    constexpr long long N1 = (long long)ND * NH / 2;
    constexpr long long N2 = (long long)NH * NC / 2;
    constexpr long long NE = (long long)NB * NS * ND / 2;
    constexpr long long P1 = NQ, P2 = 2 * NQ, P3 = 3 * NQ;
    constexpr long long P4 = P3 + N1, P5 = P4 + N2, TOT = P5 + NE;
    for (long long i = (long long)blockIdx.x * 256 + threadIdx.x; i < TOT;
         i += (long long)gridDim.x * 256) {
        if      (i < P1) oqkv[i] = __float22half2_rn(qw[i]);
        else if (i < P2) oqkv[i] = __float22half2_rn(kw[i - P1]);
        else if (i < P3) oqkv[i] = __float22half2_rn(vw[i - P2]);
        else if (i < P4) o1[i - P3] = __float22half2_rn(w1[i - P3]);
        else if (i < P5) o2[i - P4] = __float22half2_rn(w2[i - P4]);
        else {
            long long e = i - P5;                 // half2 index over [NB*NS, ND/2]
            int d2 = (int)(e & (ND / 2 - 1));
            int bs = (int)(e >> 9);
            int s  = bs & (NS - 1);
            int tok = x[bs];
            float2 a = sem[(size_t)tok * (ND / 2) + d2];
            float2 p = pos[(size_t)s   * (ND / 2) + d2];
            oh[e] = __floats2half2_rn(a.x + p.x, a.y + p.y);
        }
    }
}

// -------------------- causal softmax: fp16 scores -> fp16 probs --------------------
__global__ void softmax_kernel(const __half* __restrict__ scores, __half* __restrict__ probs) {
    const int r = blockIdx.x;
    const int q = r & (NS - 1);
    const __half* row = scores + (size_t)r * NS;
    __half* prow = probs + (size_t)r * NS;
    const int tid = threadIdx.x;
    __shared__ float red[256];

    float v[8];
    float mx = -1e30f;
    #pragma unroll
    for (int j = 0; j < 8; j++) {
        const int c = tid + j * 256;
        v[j] = __half2float(row[c]);
        if (c <= q) mx = fmaxf(mx, v[j]);
    }
    red[tid] = mx; __syncthreads();
    for (int s = 128; s > 0; s >>= 1) {
        if (tid < s) red[tid] = fmaxf(red[tid], red[tid + s]);
        __syncthreads();
    }
    mx = red[0]; __syncthreads();

    float e[8];
    float sum = 0.f;
    #pragma unroll
    for (int j = 0; j < 8; j++) {
        const int c = tid + j * 256;
        e[j] = (c <= q) ? expf(v[j] - mx) : 0.f;
        sum += e[j];
    }
    red[tid] = sum; __syncthreads();
    for (int s = 128; s > 0; s >>= 1) {
        if (tid < s) red[tid] += red[tid + s];
        __syncthreads();
    }
    const float inv = 1.f / red[0];
    #pragma unroll
    for (int j = 0; j < 8; j++)
        prow[tid + j * 256] = __float2half_rn(e[j] * inv);
}

// -------------------- layernorm: fp32 in -> fp16 out --------------------
__global__ void layernorm_kernel(const float* __restrict__ a,
                                 const float* __restrict__ g,
                                 const float* __restrict__ b,
                                 __half* __restrict__ out) {
    const int r = blockIdx.x;
    const float* row = a + (size_t)r * ND;
    __half2* orow = (__half2*)(out + (size_t)r * ND);
    const int tid = threadIdx.x;
    float4 v = ((const float4*)row)[tid];
    float s  = v.x + v.y + v.z + v.w;
    float ss = v.x*v.x + v.y*v.y + v.z*v.z + v.w*v.w;
    __shared__ float rs[256], rss[256];
    rs[tid] = s; rss[tid] = ss; __syncthreads();
    for (int st = 128; st > 0; st >>= 1) {
        if (tid < st) { rs[tid] += rs[tid + st]; rss[tid] += rss[tid + st]; }
        __syncthreads();
    }
    const float mu  = rs[0] * (1.f / ND);
    const float var = rss[0] * (1.f / ND) - mu * mu;
    const float inv = rsqrtf(var + LN_EPS);
    float4 gg = ((const float4*)g)[tid];
    float4 bb = ((const float4*)b)[tid];
    orow[tid*2]   = __floats2half2_rn((v.x - mu) * inv * gg.x + bb.x,
                                      (v.y - mu) * inv * gg.y + bb.y);
    orow[tid*2+1] = __floats2half2_rn((v.z - mu) * inv * gg.z + bb.z,
                                      (v.w - mu) * inv * gg.w + bb.w);
}

// -------------------- host --------------------
static const int SMEM_BNK = 3 * (128 * 72 + 128 * 72) * 2;   // 110592 B
static const int SMEM_KN  = 3 * (128 * 72 + 64 * 136) * 2;   // 107520 B

extern "C" void kernel_launch(void* const* d_in, const int* in_sizes, int n_in,
                              void* d_out, int out_size) {
    const int*   x    = (const int*)  d_in[0];
    const float* sem  = (const float*)d_in[1];
    const float* pos  = (const float*)d_in[2];
    // d_in[3] = F (exact identity -> skipped)
    const float* Qw   = (const float*)d_in[4];
    const float* Kw   = (const float*)d_in[5];
    const float* Vw   = (const float*)d_in[6];
    const float* ln_g = (const float*)d_in[7];
    const float* ln_b = (const float*)d_in[8];
    const float* W1   = (const float*)d_in[9];
    const float* b1   = (const float*)d_in[10];
    const float* W2   = (const float*)d_in[11];
    const float* b2   = (const float*)d_in[12];
    float* out = (float*)d_out;

    __half *h,*qkv,*p,*xn,*hid,*wqkvH,*w1H,*w2H,*sc;
    float *a;
    cudaGetSymbolAddress((void**)&h,    g_h);
    cudaGetSymbolAddress((void**)&qkv,  g_qkv);
    cudaGetSymbolAddress((void**)&p,    g_p);
    cudaGetSymbolAddress((void**)&xn,   g_xn);
    cudaGetSymbolAddress((void**)&hid,  g_hid);
    cudaGetSymbolAddress((void**)&a,    g_a);
    cudaGetSymbolAddress((void**)&sc,   g_scores);
    cudaGetSymbolAddress((void**)&wqkvH,g_wqkvH);
    cudaGetSymbolAddress((void**)&w1H,  g_w1H);
    cudaGetSymbolAddress((void**)&w2H,  g_w2H);

    __half* q = qkv;
    __half* k = qkv + (size_t)NB*NS*ND;
    __half* v = qkv + (size_t)2*NB*NS*ND;

    cudaFuncSetAttribute(mma_gemm<false,false,false,false,false,true>,  cudaFuncAttributeMaxDynamicSharedMemorySize, SMEM_KN);
    cudaFuncSetAttribute(mma_gemm<true, false,false,true, false,true>,  cudaFuncAttributeMaxDynamicSharedMemorySize, SMEM_BNK);
    cudaFuncSetAttribute(mma_gemm<false,false,false,false,true, false>, cudaFuncAttributeMaxDynamicSharedMemorySize, SMEM_KN);
    cudaFuncSetAttribute(mma_gemm<false,true, true, false,false,true>,  cudaFuncAttributeMaxDynamicSharedMemorySize, SMEM_KN);
    cudaFuncSetAttribute(mma_gemm<false,true, false,false,false,false>, cudaFuncAttributeMaxDynamicSharedMemorySize, SMEM_KN);

    const long long sQKV = (long long)NS * ND;
    const long long sSS  = (long long)NS * NS;

    // 0) fused prepass: weights -> fp16 + embeddings -> fp16
    prepass_kernel<<<65536, 256>>>((const float2*)Qw, (const float2*)Kw, (const float2*)Vw,
                                   (const float2*)W1, (const float2*)W2,
                                   x, (const float2*)sem, (const float2*)pos,
                                   (__half2*)wqkvH, (__half2*)w1H, (__half2*)w2H, (__half2*)h);

    // 1) fused QKV projection: z in {Q,K,V}; A shared, B/C strided
    mma_gemm<false,false,false,false,false,true><<<dim3((NB*NS/128)*(ND/128), 1, 3), 128, SMEM_KN>>>(
        h, wqkvH, nullptr, qkv, NB*NS, ND, ND, 1.f,
        0, (long long)ND*ND, (long long)NB*NS*ND, 16);

    // 2) scores = Q @ K^T / 32 -> fp16 (triangular grid: 136 tiles/batch)
    {
        const int Mtiles = NS / 128;
        const int tri = Mtiles * (Mtiles + 1) / 2;     // 136
        mma_gemm<true,false,false,true,false,true><<<dim3(tri, 1, NB), 128, SMEM_BNK>>>(
            q, k, nullptr, sc, NS, NS, ND, 0.03125f, sQKV, sQKV, sSS, 16);
    }

    // 3) causal softmax -> fp16 probs (single-read, register-cached)
    softmax_kernel<<<NB*NS, 256>>>(sc, p);

    // 4) a = probs @ Vx -> fp32 (causal K-chunk skip)
    mma_gemm<false,false,false,false,true,false><<<dim3((NS/128)*(ND/128), 1, NB), 128, SMEM_KN>>>(
        p, v, nullptr, a, NS, ND, NS, 1.f, sSS, sQKV, sQKV, 16);

    // 5) layernorm -> fp16
    layernorm_kernel<<<NB*NS, 256>>>(a, ln_g, ln_b, xn);

    // 6) MLP1: relu(xn @ W1 + b1) -> fp16
    mma_gemm<false,true,true,false,false,true><<<dim3((NB*NS/128)*(NH/128), 1, 1), 128, SMEM_KN>>>(
        xn, w1H, b1, hid, NB*NS, NH, ND, 1.f, 0, 0, 0, 16);

    // 7) MLP2: hid @ W2 + b2 -> fp32 out (G=32 supertile: 2 B-passes, A-slab fits L2)
    mma_gemm<false,true,false,false,false,false><<<dim3((NB*NS/128)*(NC/128), 1, 1), 128, SMEM_KN>>>(
        hid, w2H, b2, out, NB*NS, NC, NH, 1.f, 0, 0, 0, 32);
}